// round 3
// baseline (speedup 1.0000x reference)
#include <cuda_runtime.h>
#include <cuda_bf16.h>

// Dead-code-eliminated Net2 BSDE recurrence.
// ARITHMETIC IS BIT-FROZEN TO THE ROUND-1 PASSING VERSION: the recurrence is
// chaotic near u=50 (mid-branch slope ~1852), so any reassociation/refolding
// changes the trajectory by >1e-3. Only bit-neutral latency optimizations here:
//  - drift branches evaluated unconditionally (verbatim expressions) + ternary
//    select, removing divergence from the 40-step dependent chain
//  - tlist staged to shared, u0 prefetched before the barrier
//  - phase-1 dot products identical: 32-lane stride + 5-level shuffle tree

#define D_DIM   100
#define N_STEPS 40
#define NWARPS  8
#define NTHREADS (NWARPS * 32)

__device__ __forceinline__ float drift_f(float u) {
    // Verbatim Round-1 branch expressions; branchless select (bit-identical
    // values, no BSSY/BSYNC in the serial chain).
    float low  = -0.02f * u / 3.0f - 0.02f * u;
    float high = -0.002f * u / 3.0f - 0.02f * u;
    float mid  = -(70.0f - 50.0f) / (0.02f - 0.2f) * (u - 50.0f) / 3.0f * u
                 - 0.2f / 3.0f * u - 0.02f * u;
    return (u < 50.0f) ? low : ((u >= 70.0f) ? high : mid);
}

__global__ void net2_u_kernel(const float* __restrict__ x0,
                              const float* __restrict__ tlist,
                              const float* __restrict__ noise,   // (N_STEPS, D, 1)
                              const float* __restrict__ u0,
                              const float* __restrict__ gu0,     // (D, 1)
                              float* __restrict__ out) {
    __shared__ float term3[N_STEPS];
    __shared__ float s_dt[N_STEPS];

    const int tid  = threadIdx.x;
    const int warp = tid >> 5;
    const int lane = tid & 31;

    // Stage tlist into shared (bit-identical copy).
    if (tid < N_STEPS) s_dt[tid] = tlist[tid];

    // Each warp computes dot(gu, dW1_k) for steps k = warp, warp+8, ...
    // EXACT Round-1 ordering: lane-stride 32, 5-deep full-warp shuffle tree.
    for (int k = warp; k < N_STEPS; k += NWARPS) {
        float s = 0.0f;
        const float* nk = noise + k * D_DIM;
        #pragma unroll
        for (int i = lane; i < D_DIM; i += 32) {
            float gu_i = 0.2f * x0[i] * gu0[i];
            s += gu_i * nk[i];
        }
        #pragma unroll
        for (int off = 16; off > 0; off >>= 1)
            s += __shfl_down_sync(0xFFFFFFFFu, s, off);
        if (lane == 0)
            term3[k] = s * sqrtf(tlist[k]);
    }

    // Prefetch u0 before the barrier (independent of phase 1).
    float u = 0.0f;
    if (tid == 0) u = u0[0];

    __syncthreads();

    if (tid == 0) {
        #pragma unroll
        for (int k = 0; k < N_STEPS; k++) {
            float dt = s_dt[k];
            u = u - drift_f(u) * dt + term3[k];   // verbatim Round-1 update
        }
        out[0] = u;
    }
}

extern "C" void kernel_launch(void* const* d_in, const int* in_sizes, int n_in,
                              void* d_out, int out_size) {
    const float* x0    = (const float*)d_in[0];
    const float* tlist = (const float*)d_in[1];
    const float* noise = (const float*)d_in[2];
    const float* u0    = (const float*)d_in[3];
    const float* gu0   = (const float*)d_in[4];
    float* out = (float*)d_out;

    net2_u_kernel<<<1, NTHREADS>>>(x0, tlist, noise, u0, gu0, out);
}

// round 4
// speedup vs baseline: 1.1481x; 1.1481x over previous
#include <cuda_runtime.h>
#include <cuda_bf16.h>

// Dead-code-eliminated Net2 BSDE recurrence.
// ARITHMETIC IS BIT-FROZEN TO THE ROUND-1/3 PASSING VERSION (rel_err
// 1.627573e-05): the recurrence is chaotic near u=50 (mid-branch slope ~1852),
// so any rounding change blows past 1e-3. The per-step dot product
// (lane-stride-32 accumulate + 5-level shuffle tree + s*sqrtf(dt)) and the
// serial u-update are byte-identical to Round 3.
//
// Round-4 change (bit-neutral): warp->step mapping widened from 8 warps x 5
// sequential steps to 32 warps (1024 threads), max 2 sequential steps/warp.
// Phase-1 critical path shrinks by ~3 dot+shuffle rounds; the barrier releases
// earlier. Which warp computes a step cannot affect its bits.

#define D_DIM   100
#define N_STEPS 40
#define NWARPS  32
#define NTHREADS (NWARPS * 32)   // 1024

__device__ __forceinline__ float drift_f(float u) {
    // Verbatim frozen branch expressions; branchless select (bit-identical).
    float low  = -0.02f * u / 3.0f - 0.02f * u;
    float high = -0.002f * u / 3.0f - 0.02f * u;
    float mid  = -(70.0f - 50.0f) / (0.02f - 0.2f) * (u - 50.0f) / 3.0f * u
                 - 0.2f / 3.0f * u - 0.02f * u;
    return (u < 50.0f) ? low : ((u >= 70.0f) ? high : mid);
}

__global__ void net2_u_kernel(const float* __restrict__ x0,
                              const float* __restrict__ tlist,
                              const float* __restrict__ noise,   // (N_STEPS, D, 1)
                              const float* __restrict__ u0,
                              const float* __restrict__ gu0,     // (D, 1)
                              float* __restrict__ out) {
    __shared__ float term3[N_STEPS];
    __shared__ float s_dt[N_STEPS];

    const int tid  = threadIdx.x;
    const int warp = tid >> 5;
    const int lane = tid & 31;

    // Stage tlist into shared (bit-identical copy).
    if (tid < N_STEPS) s_dt[tid] = tlist[tid];

    // Warps 0-7 handle steps {w, w+32}; warps 8-31 handle step {w}.
    // EXACT frozen per-step arithmetic: lane-stride 32, 5-deep shuffle tree.
    for (int k = warp; k < N_STEPS; k += NWARPS) {
        float s = 0.0f;
        const float* nk = noise + k * D_DIM;
        #pragma unroll
        for (int i = lane; i < D_DIM; i += 32) {
            float gu_i = 0.2f * x0[i] * gu0[i];
            s += gu_i * nk[i];
        }
        #pragma unroll
        for (int off = 16; off > 0; off >>= 1)
            s += __shfl_down_sync(0xFFFFFFFFu, s, off);
        if (lane == 0)
            term3[k] = s * sqrtf(tlist[k]);
    }

    // Prefetch u0 before the barrier (independent of phase 1).
    float u = 0.0f;
    if (tid == 0) u = u0[0];

    __syncthreads();

    if (tid == 0) {
        #pragma unroll
        for (int k = 0; k < N_STEPS; k++) {
            float dt = s_dt[k];
            u = u - drift_f(u) * dt + term3[k];   // verbatim frozen update
        }
        out[0] = u;
    }
}

extern "C" void kernel_launch(void* const* d_in, const int* in_sizes, int n_in,
                              void* d_out, int out_size) {
    const float* x0    = (const float*)d_in[0];
    const float* tlist = (const float*)d_in[1];
    const float* noise = (const float*)d_in[2];
    const float* u0    = (const float*)d_in[3];
    const float* gu0   = (const float*)d_in[4];
    float* out = (float*)d_out;

    net2_u_kernel<<<1, NTHREADS>>>(x0, tlist, noise, u0, gu0, out);
}

// round 5
// speedup vs baseline: 1.5742x; 1.3711x over previous
#include <cuda_runtime.h>
#include <cuda_bf16.h>

// Dead-code-eliminated Net2 BSDE recurrence.
// ARITHMETIC IS BIT-FROZEN to the passing trajectory (rel_err 1.627573e-05):
// the recurrence is chaotic near u=50, so any rounding change blows past 1e-3.
//
// Round-5 changes:
//  - div3(x): correctly-rounded x/3 via the Brisebarre-Muller two-FMA
//    constant multiply (C_HI = RN(1/3), C_LO = RN(1/3 - C_HI) = -1/(3*2^25)).
//    RN(x * 1/3) == RN(x / 3), so when the scheme rounds correctly (it does
//    for essentially all binary32 inputs) this is BIT-IDENTICAL to FDIV while
//    cutting the serial chain by ~25-50 cyc/iteration. rel_err must come back
//    as exactly 1.627573e-05 -- that's the verification gate.
//  - warps 0-7 interleave their two dot-product rounds (ILP; per-step
//    arithmetic and shuffle-tree order unchanged -> bit-neutral).

#define D_DIM   100
#define N_STEPS 40
#define NWARPS  32
#define NTHREADS (NWARPS * 32)   // 1024

__device__ __forceinline__ float div3(float x) {
    const float C_HI = 0.33333334f;       // RN(1/3)
    const float C_LO = -9.9341075e-09f;   // RN(1/3 - C_HI) = -1/(3*2^25)
    return __fmaf_rn(x, C_HI, x * C_LO);
}

__device__ __forceinline__ float drift_f(float u) {
    // Frozen branch values; /3.0f replaced by bit-equivalent div3.
    float low  = div3(-0.02f * u) - 0.02f * u;
    float high = div3(-0.002f * u) - 0.02f * u;
    // -(70-50)/(0.02-0.2) and 0.2f/3.0f are compile-time constants in the
    // frozen version; keep the same folded values.
    float mid  = div3(-(70.0f - 50.0f) / (0.02f - 0.2f) * (u - 50.0f)) * u
                 - (0.2f / 3.0f) * u - 0.02f * u;
    return (u < 50.0f) ? low : ((u >= 70.0f) ? high : mid);
}

__global__ void net2_u_kernel(const float* __restrict__ x0,
                              const float* __restrict__ tlist,
                              const float* __restrict__ noise,   // (N_STEPS, D, 1)
                              const float* __restrict__ u0,
                              const float* __restrict__ gu0,     // (D, 1)
                              float* __restrict__ out) {
    __shared__ float term3[N_STEPS];
    __shared__ float s_dt[N_STEPS];

    const int tid  = threadIdx.x;
    const int warp = tid >> 5;
    const int lane = tid & 31;

    if (tid < N_STEPS) s_dt[tid] = tlist[tid];

    // Frozen per-step dot: lane-stride 32 accumulate + 5-level shuffle tree
    // + s * sqrtf(tlist[k]). Warps 0-7 run two steps INTERLEAVED (same bits,
    // better ILP); warps 8-31 run one.
    if (warp < 8) {
        const int k0 = warp, k1 = warp + 32;
        float s0 = 0.0f, s1 = 0.0f;
        const float* n0 = noise + k0 * D_DIM;
        const float* n1 = noise + k1 * D_DIM;
        #pragma unroll
        for (int i = lane; i < D_DIM; i += 32) {
            float gu_i = 0.2f * x0[i] * gu0[i];
            s0 += gu_i * n0[i];
            s1 += gu_i * n1[i];
        }
        #pragma unroll
        for (int off = 16; off > 0; off >>= 1) {
            s0 += __shfl_down_sync(0xFFFFFFFFu, s0, off);
            s1 += __shfl_down_sync(0xFFFFFFFFu, s1, off);
        }
        if (lane == 0) {
            term3[k0] = s0 * sqrtf(tlist[k0]);
            term3[k1] = s1 * sqrtf(tlist[k1]);
        }
    } else {
        const int k = warp;
        float s = 0.0f;
        const float* nk = noise + k * D_DIM;
        #pragma unroll
        for (int i = lane; i < D_DIM; i += 32) {
            float gu_i = 0.2f * x0[i] * gu0[i];
            s += gu_i * nk[i];
        }
        #pragma unroll
        for (int off = 16; off > 0; off >>= 1)
            s += __shfl_down_sync(0xFFFFFFFFu, s, off);
        if (lane == 0)
            term3[k] = s * sqrtf(tlist[k]);
    }

    float u = 0.0f;
    if (tid == 0) u = u0[0];

    __syncthreads();

    if (tid == 0) {
        #pragma unroll
        for (int k = 0; k < N_STEPS; k++) {
            float dt = s_dt[k];
            u = u - drift_f(u) * dt + term3[k];   // frozen update shape
        }
        out[0] = u;
    }
}

extern "C" void kernel_launch(void* const* d_in, const int* in_sizes, int n_in,
                              void* d_out, int out_size) {
    const float* x0    = (const float*)d_in[0];
    const float* tlist = (const float*)d_in[1];
    const float* noise = (const float*)d_in[2];
    const float* u0    = (const float*)d_in[3];
    const float* gu0   = (const float*)d_in[4];
    float* out = (float*)d_out;

    net2_u_kernel<<<1, NTHREADS>>>(x0, tlist, noise, u0, gu0, out);
}